// round 5
// baseline (speedup 1.0000x reference)
#include <cuda_runtime.h>
#include <cuda_fp16.h>
#include <math.h>

#define NN 50000
#define EE 800000
#define NF0 128
#define NF1 64
#define NF2 40
#define NCH 49   /* ceil(NN/1024) */

// ---------------- scratch (__device__ globals; allocation-free) ----------------
__device__ __align__(256) __half g_P0h[NN * NF0];  // fp16: M ⊙ (x @ W0)
__device__ __align__(256) float  g_S0[NN * NF0];   // fp32: spmm(adjZ, P0)
__device__ __align__(256) __half g_P1h[NN * NF1];  // fp16: M ⊙ (h0 @ W1)
__device__ __align__(256) float  g_S1[NN * NF1];   // fp32: spmm(adjZ, P1)
__device__ __align__(256) __half g_P2h[NN * NF2];  // fp16: h1 @ W2
__device__ __align__(256) int    g_rp[NN + 1];
__device__ __align__(256) int    g_deg[NN];
__device__ __align__(256) int    g_cur[NN];
__device__ __align__(256) int4   g_edge[EE];       // {col, vZ bits, vA bits, 0}
__device__ __align__(256) int    g_part[NCH];

// ---------------- helpers ----------------
__device__ __forceinline__ unsigned f2tf(float f) {
    unsigned u;
    asm("cvt.rna.tf32.f32 %0, %1;" : "=r"(u) : "f"(f));
    return u;
}

__device__ __forceinline__ void mma_tf32(float c[4],
                                         const unsigned a[4],
                                         const unsigned b[2]) {
    asm volatile(
        "mma.sync.aligned.m16n8k8.row.col.f32.tf32.tf32.f32 "
        "{%0,%1,%2,%3}, {%4,%5,%6,%7}, {%8,%9}, {%0,%1,%2,%3};"
        : "+f"(c[0]), "+f"(c[1]), "+f"(c[2]), "+f"(c[3])
        : "r"(a[0]), "r"(a[1]), "r"(a[2]), "r"(a[3]), "r"(b[0]), "r"(b[1]));
}

// ---------------- CSR build ----------------
__global__ void k_zero() {
    int i = blockIdx.x * blockDim.x + threadIdx.x;
    int stride = gridDim.x * blockDim.x;
    for (int j = i; j < NN; j += stride) { g_deg[j] = 0; g_cur[j] = 0; }
    if (i == 0) g_rp[NN] = EE;
}

__global__ void k_hist(const int* __restrict__ row) {
    int e = blockIdx.x * blockDim.x + threadIdx.x;
    if (e < EE) atomicAdd(&g_deg[row[e]], 1);
}

__global__ void k_scan1() {   // per-chunk sums (chunk = 1024)
    __shared__ int sred[8];
    int base = blockIdx.x * 1024;
    int local = 0;
    #pragma unroll
    for (int j = 0; j < 4; ++j) {
        int i = base + threadIdx.x + j * 256;
        if (i < NN) local += g_deg[i];
    }
    for (int off = 16; off; off >>= 1) local += __shfl_down_sync(0xffffffffu, local, off);
    if ((threadIdx.x & 31) == 0) sred[threadIdx.x >> 5] = local;
    __syncthreads();
    if (threadIdx.x == 0) {
        int s = 0;
        #pragma unroll
        for (int w = 0; w < 8; ++w) s += sred[w];
        g_part[blockIdx.x] = s;
    }
}

__global__ void k_scan2() {   // parallel exclusive scan of 49 partials
    __shared__ int s[64];
    int t = threadIdx.x;
    int v = (t < NCH) ? g_part[t] : 0;
    s[t] = v;
    __syncthreads();
    for (int off = 1; off < 64; off <<= 1) {
        int u = (t >= off) ? s[t - off] : 0;
        __syncthreads();
        s[t] += u;
        __syncthreads();
    }
    if (t < NCH) g_part[t] = s[t] - v;
}

__global__ void k_scan3() {   // per-chunk exclusive scan + offset
    __shared__ int s[1024];
    int i = blockIdx.x * 1024 + threadIdx.x;
    int v = (i < NN) ? g_deg[i] : 0;
    s[threadIdx.x] = v;
    __syncthreads();
    for (int off = 1; off < 1024; off <<= 1) {
        int t = (threadIdx.x >= (unsigned)off) ? s[threadIdx.x - off] : 0;
        __syncthreads();
        s[threadIdx.x] += t;
        __syncthreads();
    }
    if (i < NN) g_rp[i] = g_part[blockIdx.x] + s[threadIdx.x] - v;
}

__global__ void k_scatter(const int* __restrict__ row, const int* __restrict__ col,
                          const float* __restrict__ vZ, const float* __restrict__ vA) {
    int e = blockIdx.x * blockDim.x + threadIdx.x;
    if (e >= EE) return;
    int r = row[e];
    int pos = g_rp[r] + atomicAdd(&g_cur[r], 1);
    int4 ed;
    ed.x = col[e];
    ed.y = __float_as_int(vZ[e]);
    ed.z = __float_as_int(vA[e]);
    ed.w = 0;
    g_edge[pos] = ed;
}

// ======== GEMM 0 (tf32 tensor core): P0 = M ⊙ (x @ W0), 50000x128x128 ========
// block tile 128x128, 256 threads (8 warps in 2(m) x 4(n)); warp tile 64x32.
__global__ void __launch_bounds__(256) k_gemm0(const float* __restrict__ x,
                                               const float* __restrict__ W0,
                                               const float* __restrict__ M) {
    __shared__ float As[128 * 32];   // [m][k^swz], swz = (m&3)<<3
    __shared__ float Bs[32 * 128];   // [k][n^swz], swz = (k&3)<<3
    int r0 = blockIdx.x * 128;
    int tid = threadIdx.x;
    int lane = tid & 31, wid = tid >> 5;
    int m0w = (wid & 1) * 64;
    int n0w = (wid >> 1) * 32;
    int g = lane >> 2, t = lane & 3;

    float acc[4][4][4];
    #pragma unroll
    for (int i = 0; i < 4; ++i)
        #pragma unroll
        for (int j = 0; j < 4; ++j)
            #pragma unroll
            for (int c = 0; c < 4; ++c) acc[i][j][c] = 0.f;

    const float4* xv = (const float4*)x;
    const float4* wv = (const float4*)W0;

    for (int kc = 0; kc < 128; kc += 32) {
        __syncthreads();
        // stage A (128 rows x 32 k), tf32-rounded, swizzled
        #pragma unroll
        for (int it = 0; it < 4; ++it) {
            int i = tid + it * 256;
            int rr = i >> 3, c4 = i & 7;
            int gr = r0 + rr;
            float4 v = (gr < NN) ? xv[gr * 32 + (kc >> 2) + c4]
                                 : make_float4(0.f, 0.f, 0.f, 0.f);
            float4 o;
            o.x = __uint_as_float(f2tf(v.x));
            o.y = __uint_as_float(f2tf(v.y));
            o.z = __uint_as_float(f2tf(v.z));
            o.w = __uint_as_float(f2tf(v.w));
            *(float4*)&As[rr * 32 + ((c4 * 4) ^ ((rr & 3) << 3))] = o;
        }
        // stage B (32 k x 128 n)
        #pragma unroll
        for (int it = 0; it < 4; ++it) {
            int i = tid + it * 256;
            int kr = i >> 5, c4 = i & 31;
            float4 v = wv[(kc + kr) * 32 + c4];
            float4 o;
            o.x = __uint_as_float(f2tf(v.x));
            o.y = __uint_as_float(f2tf(v.y));
            o.z = __uint_as_float(f2tf(v.z));
            o.w = __uint_as_float(f2tf(v.w));
            *(float4*)&Bs[kr * 128 + ((c4 * 4) ^ ((kr & 3) << 3))] = o;
        }
        __syncthreads();

        #pragma unroll
        for (int k8 = 0; k8 < 32; k8 += 8) {
            unsigned af[4][4], bf[4][2];
            #pragma unroll
            for (int mt = 0; mt < 4; ++mt) {
                int m = m0w + mt * 16 + g;
                int sw = (m & 3) << 3;
                af[mt][0] = __float_as_uint(As[m * 32 + ((k8 + t) ^ sw)]);
                af[mt][1] = __float_as_uint(As[(m + 8) * 32 + ((k8 + t) ^ sw)]);
                af[mt][2] = __float_as_uint(As[m * 32 + ((k8 + t + 4) ^ sw)]);
                af[mt][3] = __float_as_uint(As[(m + 8) * 32 + ((k8 + t + 4) ^ sw)]);
            }
            #pragma unroll
            for (int nt = 0; nt < 4; ++nt) {
                int n = n0w + nt * 8 + g;
                bf[nt][0] = __float_as_uint(Bs[(k8 + t) * 128 + (n ^ (t << 3))]);
                bf[nt][1] = __float_as_uint(Bs[(k8 + t + 4) * 128 + (n ^ (t << 3))]);
            }
            #pragma unroll
            for (int mt = 0; mt < 4; ++mt)
                #pragma unroll
                for (int nt = 0; nt < 4; ++nt)
                    mma_tf32(acc[mt][nt], af[mt], bf[nt]);
        }
    }

    // epilogue: scale by M[row], store fp16
    #pragma unroll
    for (int mt = 0; mt < 4; ++mt) {
        int rlo = r0 + m0w + mt * 16 + g;
        int rhi = rlo + 8;
        float mlo = (rlo < NN) ? M[rlo] : 0.f;
        float mhi = (rhi < NN) ? M[rhi] : 0.f;
        #pragma unroll
        for (int nt = 0; nt < 4; ++nt) {
            int cc = n0w + nt * 8 + 2 * t;
            if (rlo < NN) {
                float2 o; o.x = mlo * acc[mt][nt][0]; o.y = mlo * acc[mt][nt][1];
                *(__half2*)&g_P0h[rlo * 128 + cc] = __floats2half2_rn(o.x, o.y);
            }
            if (rhi < NN) {
                float2 o; o.x = mhi * acc[mt][nt][2]; o.y = mhi * acc[mt][nt][3];
                *(__half2*)&g_P0h[rhi * 128 + cc] = __floats2half2_rn(o.x, o.y);
            }
        }
    }
}

// -------- spmm width 128 (fp16 gather): S0[r] = sum vZ * P0h[col] --------
__global__ void __launch_bounds__(256) k_spmm128() {
    int w = (blockIdx.x * 256 + threadIdx.x) >> 5;
    int lane = threadIdx.x & 31;
    if (w >= NN) return;
    int s = g_rp[w], e = g_rp[w + 1];
    float a0 = 0.f, a1 = 0.f, a2 = 0.f, a3 = 0.f;
    const uint2* Xv = (const uint2*)g_P0h;   // 4 halves per uint2; 32 uint2 per row
    int j = s;
    for (; j + 1 < e; j += 2) {
        int4 e0 = g_edge[j], e1 = g_edge[j + 1];
        float v0 = __int_as_float(e0.y), v1 = __int_as_float(e1.y);
        uint2 pa = Xv[e0.x * 32 + lane];
        uint2 pb = Xv[e1.x * 32 + lane];
        float2 pa0 = __half22float2(*(__half2*)&pa.x);
        float2 pa1 = __half22float2(*(__half2*)&pa.y);
        float2 pb0 = __half22float2(*(__half2*)&pb.x);
        float2 pb1 = __half22float2(*(__half2*)&pb.y);
        a0 += v0 * pa0.x + v1 * pb0.x;
        a1 += v0 * pa0.y + v1 * pb0.y;
        a2 += v0 * pa1.x + v1 * pb1.x;
        a3 += v0 * pa1.y + v1 * pb1.y;
    }
    if (j < e) {
        int4 e0 = g_edge[j];
        float v0 = __int_as_float(e0.y);
        uint2 pa = Xv[e0.x * 32 + lane];
        float2 pa0 = __half22float2(*(__half2*)&pa.x);
        float2 pa1 = __half22float2(*(__half2*)&pa.y);
        a0 += v0 * pa0.x; a1 += v0 * pa0.y; a2 += v0 * pa1.x; a3 += v0 * pa1.y;
    }
    float4 o; o.x = a0; o.y = a1; o.z = a2; o.w = a3;
    ((float4*)g_S0)[w * 32 + lane] = o;
}

// == GEMM 1 (tf32): P1 = M ⊙ (relu(AM⊙S0 + b0) @ W1), 50000x64x128 ==
// block tile 128x64, 256 threads (8 warps in 4(m) x 2(n)); warp tile 32x32.
__global__ void __launch_bounds__(256) k_gemm1(const float* __restrict__ AM,
                                               const float* __restrict__ b0,
                                               const float* __restrict__ W1,
                                               const float* __restrict__ M) {
    __shared__ float As[128 * 32];   // relu(AM*S0+b0), tf32 bits
    __shared__ float Bs[32 * 64];
    int r0 = blockIdx.x * 128;
    int tid = threadIdx.x;
    int lane = tid & 31, wid = tid >> 5;
    int m0w = (wid & 3) * 32;
    int n0w = (wid >> 2) * 32;
    int g = lane >> 2, t = lane & 3;

    float acc[2][4][4];
    #pragma unroll
    for (int i = 0; i < 2; ++i)
        #pragma unroll
        for (int j = 0; j < 4; ++j)
            #pragma unroll
            for (int c = 0; c < 4; ++c) acc[i][j][c] = 0.f;

    const float4* sv = (const float4*)g_S0;
    const float4* bv = (const float4*)b0;
    const float4* wv = (const float4*)W1;

    for (int kc = 0; kc < 128; kc += 32) {
        __syncthreads();
        // stage A with fused relu(AM*s + b0)
        #pragma unroll
        for (int it = 0; it < 4; ++it) {
            int i = tid + it * 256;
            int rr = i >> 3, c4 = i & 7;
            int gr = r0 + rr;
            float4 o = make_float4(0.f, 0.f, 0.f, 0.f);
            if (gr < NN) {
                float4 s4 = sv[gr * 32 + (kc >> 2) + c4];
                float4 bb = bv[(kc >> 2) + c4];
                float am = AM[gr];
                o.x = fmaxf(fmaf(am, s4.x, bb.x), 0.f);
                o.y = fmaxf(fmaf(am, s4.y, bb.y), 0.f);
                o.z = fmaxf(fmaf(am, s4.z, bb.z), 0.f);
                o.w = fmaxf(fmaf(am, s4.w, bb.w), 0.f);
            }
            o.x = __uint_as_float(f2tf(o.x));
            o.y = __uint_as_float(f2tf(o.y));
            o.z = __uint_as_float(f2tf(o.z));
            o.w = __uint_as_float(f2tf(o.w));
            *(float4*)&As[rr * 32 + ((c4 * 4) ^ ((rr & 3) << 3))] = o;
        }
        // stage B (32 k x 64 n)
        #pragma unroll
        for (int it = 0; it < 2; ++it) {
            int i = tid + it * 256;
            int kr = i >> 4, c4 = i & 15;
            float4 v = wv[(kc + kr) * 16 + c4];
            float4 o;
            o.x = __uint_as_float(f2tf(v.x));
            o.y = __uint_as_float(f2tf(v.y));
            o.z = __uint_as_float(f2tf(v.z));
            o.w = __uint_as_float(f2tf(v.w));
            *(float4*)&Bs[kr * 64 + ((c4 * 4) ^ ((kr & 3) << 3))] = o;
        }
        __syncthreads();

        #pragma unroll
        for (int k8 = 0; k8 < 32; k8 += 8) {
            unsigned af[2][4], bf[4][2];
            #pragma unroll
            for (int mt = 0; mt < 2; ++mt) {
                int m = m0w + mt * 16 + g;
                int sw = (m & 3) << 3;
                af[mt][0] = __float_as_uint(As[m * 32 + ((k8 + t) ^ sw)]);
                af[mt][1] = __float_as_uint(As[(m + 8) * 32 + ((k8 + t) ^ sw)]);
                af[mt][2] = __float_as_uint(As[m * 32 + ((k8 + t + 4) ^ sw)]);
                af[mt][3] = __float_as_uint(As[(m + 8) * 32 + ((k8 + t + 4) ^ sw)]);
            }
            #pragma unroll
            for (int nt = 0; nt < 4; ++nt) {
                int n = n0w + nt * 8 + g;
                bf[nt][0] = __float_as_uint(Bs[(k8 + t) * 64 + (n ^ (t << 3))]);
                bf[nt][1] = __float_as_uint(Bs[(k8 + t + 4) * 64 + (n ^ (t << 3))]);
            }
            #pragma unroll
            for (int mt = 0; mt < 2; ++mt)
                #pragma unroll
                for (int nt = 0; nt < 4; ++nt)
                    mma_tf32(acc[mt][nt], af[mt], bf[nt]);
        }
    }

    #pragma unroll
    for (int mt = 0; mt < 2; ++mt) {
        int rlo = r0 + m0w + mt * 16 + g;
        int rhi = rlo + 8;
        float mlo = (rlo < NN) ? M[rlo] : 0.f;
        float mhi = (rhi < NN) ? M[rhi] : 0.f;
        #pragma unroll
        for (int nt = 0; nt < 4; ++nt) {
            int cc = n0w + nt * 8 + 2 * t;
            if (rlo < NN)
                *(__half2*)&g_P1h[rlo * 64 + cc] =
                    __floats2half2_rn(mlo * acc[mt][nt][0], mlo * acc[mt][nt][1]);
            if (rhi < NN)
                *(__half2*)&g_P1h[rhi * 64 + cc] =
                    __floats2half2_rn(mhi * acc[mt][nt][2], mhi * acc[mt][nt][3]);
        }
    }
}

// ---------------- spmm width 64 (fp16 gather) ----------------
__global__ void __launch_bounds__(256) k_spmm64() {
    int w = (blockIdx.x * 256 + threadIdx.x) >> 5;
    int lane = threadIdx.x & 31;
    if (w >= NN) return;
    int s = g_rp[w], e = g_rp[w + 1];
    float ax = 0.f, ay = 0.f;
    const __half2* Xv = (const __half2*)g_P1h;   // 32 half2 per row
    int j = s;
    for (; j + 1 < e; j += 2) {
        int4 e0 = g_edge[j], e1 = g_edge[j + 1];
        float v0 = __int_as_float(e0.y), v1 = __int_as_float(e1.y);
        float2 a = __half22float2(Xv[e0.x * 32 + lane]);
        float2 b = __half22float2(Xv[e1.x * 32 + lane]);
        ax += v0 * a.x + v1 * b.x;
        ay += v0 * a.y + v1 * b.y;
    }
    if (j < e) {
        int4 e0 = g_edge[j];
        float v = __int_as_float(e0.y);
        float2 a = __half22float2(Xv[e0.x * 32 + lane]);
        ax += v * a.x; ay += v * a.y;
    }
    float2 o; o.x = ax; o.y = ay;
    ((float2*)g_S1)[w * 32 + lane] = o;
}

// ------- GEMM 2: P2 = relu(AM⊙S1 + b1) @ W2, K=64, NO=40 (scalar) -------
__global__ void __launch_bounds__(256) k_gemm2(const float* __restrict__ AM,
                                               const float* __restrict__ b1,
                                               const float* __restrict__ W2) {
    __shared__ float Xs[32][68];
    __shared__ float Ws[64 * 40];
    int r0 = blockIdx.x * 32;
    int tid = threadIdx.x;
    const float4* sv4 = (const float4*)g_S1;
    const float4* bv4 = (const float4*)b1;
    for (int i = tid; i < 512; i += 256) {
        int rr = i >> 4, c4 = i & 15;
        int gr = r0 + rr;
        float4 v = make_float4(0.f, 0.f, 0.f, 0.f);
        if (gr < NN) {
            float4 sIn = sv4[gr * 16 + c4];
            float4 bb  = bv4[c4];
            float  am  = AM[gr];
            v.x = fmaxf(fmaf(am, sIn.x, bb.x), 0.f);
            v.y = fmaxf(fmaf(am, sIn.y, bb.y), 0.f);
            v.z = fmaxf(fmaf(am, sIn.z, bb.z), 0.f);
            v.w = fmaxf(fmaf(am, sIn.w, bb.w), 0.f);
        }
        Xs[rr][c4 * 4 + 0] = v.x;
        Xs[rr][c4 * 4 + 1] = v.y;
        Xs[rr][c4 * 4 + 2] = v.z;
        Xs[rr][c4 * 4 + 3] = v.w;
    }
    for (int i = tid; i < 64 * 40; i += 256) Ws[i] = W2[i];
    __syncthreads();
    int row = tid >> 3, cg = tid & 7;
    float acc[5] = {0.f, 0.f, 0.f, 0.f, 0.f};
    #pragma unroll 4
    for (int k = 0; k < 64; ++k) {
        float xv = Xs[row][k];
        #pragma unroll
        for (int j = 0; j < 5; ++j) acc[j] += xv * Ws[k * 40 + cg * 5 + j];
    }
    int gr = r0 + row;
    if (gr < NN) {
        #pragma unroll
        for (int j = 0; j < 5; ++j)
            g_P2h[gr * 40 + cg * 5 + j] = __float2half_rn(acc[j]);
    }
}

// ------- spmm width 40 on adj (fp16 gather) + b2 + fused log_softmax -------
__global__ void __launch_bounds__(256) k_spmm40_lsm(const float* __restrict__ b2,
                                                    float* __restrict__ out) {
    int w = (blockIdx.x * 256 + threadIdx.x) >> 5;
    int lane = threadIdx.x & 31;
    if (w >= NN) return;
    int s = g_rp[w], e = g_rp[w + 1];
    bool act = lane < 20;
    float ax = 0.f, ay = 0.f;
    for (int j = s; j < e; ++j) {
        int4 ed = g_edge[j];
        float v = __int_as_float(ed.z);   // vA
        if (act) {
            float2 a = __half22float2(*(const __half2*)&g_P2h[ed.x * 40 + 2 * lane]);
            ax += v * a.x;
            ay += v * a.y;
        }
    }
    if (act) {
        ax += b2[2 * lane];
        ay += b2[2 * lane + 1];
    }
    float m = act ? fmaxf(ax, ay) : -INFINITY;
    for (int off = 16; off; off >>= 1) m = fmaxf(m, __shfl_xor_sync(0xffffffffu, m, off));
    float sum = act ? (expf(ax - m) + expf(ay - m)) : 0.f;
    for (int off = 16; off; off >>= 1) sum += __shfl_xor_sync(0xffffffffu, sum, off);
    float lse = m + logf(sum);
    if (act) {
        float2 o;
        o.x = ax - lse;
        o.y = ay - lse;
        *(float2*)&out[w * 40 + 2 * lane] = o;
    }
}

// ---------------- launch ----------------
extern "C" void kernel_launch(void* const* d_in, const int* in_sizes, int n_in,
                              void* d_out, int out_size) {
    const float* x    = (const float*)d_in[0];
    const float* M    = (const float*)d_in[1];
    const float* AM   = (const float*)d_in[2];
    const float* adjv = (const float*)d_in[3];
    const float* adjZ = (const float*)d_in[4];
    const float* W0   = (const float*)d_in[5];
    const float* b0   = (const float*)d_in[6];
    const float* W1   = (const float*)d_in[7];
    const float* b1   = (const float*)d_in[8];
    const float* W2   = (const float*)d_in[9];
    const float* b2   = (const float*)d_in[10];
    const int*   row  = (const int*)d_in[11];
    const int*   col  = (const int*)d_in[12];
    float* out = (float*)d_out;

    (void)in_sizes; (void)n_in; (void)out_size;

    // CSR build
    k_zero<<<98, 512>>>();
    k_hist<<<(EE + 255) / 256, 256>>>(row);
    k_scan1<<<NCH, 256>>>();
    k_scan2<<<1, 64>>>();
    k_scan3<<<NCH, 1024>>>();
    k_scatter<<<(EE + 255) / 256, 256>>>(row, col, adjZ, adjv);

    // layer 0
    k_gemm0<<<(NN + 127) / 128, 256>>>(x, W0, M);
    k_spmm128<<<(NN + 7) / 8, 256>>>();
    // layer 1
    k_gemm1<<<(NN + 127) / 128, 256>>>(AM, b0, W1, M);
    k_spmm64<<<(NN + 7) / 8, 256>>>();
    // layer 2
    k_gemm2<<<(NN + 31) / 32, 256>>>(AM, b1, W2);
    k_spmm40_lsm<<<(NN + 7) / 8, 256>>>(b2, out);
}

// round 7
// speedup vs baseline: 1.3045x; 1.3045x over previous
#include <cuda_runtime.h>
#include <math.h>

#define NN 50000
#define EE 800000
#define NF0 128
#define NF1 64
#define NF2 40
#define NCH 49   /* ceil(NN/1024) */

// ---------------- scratch (__device__ globals; allocation-free) ----------------
__device__ __align__(256) float g_P0[NN * NF0];   // M ⊙ (x @ W0)
__device__ __align__(256) float g_S0[NN * NF0];   // spmm(adjZ, P0)
__device__ __align__(256) float g_P1[NN * NF1];   // M ⊙ (h0 @ W1)
__device__ __align__(256) float g_S1[NN * NF1];   // spmm(adjZ, P1)
__device__ __align__(256) float g_P2[NN * NF2];   // h1 @ W2
__device__ __align__(256) int   g_rp[NN + 1];
__device__ __align__(256) int   g_deg[NN];
__device__ __align__(256) int   g_cur[NN];
__device__ __align__(256) int   g_colP[EE];
__device__ __align__(256) float g_vZ[EE];
__device__ __align__(256) float g_vA[EE];
__device__ __align__(256) int   g_part[NCH];

// ---------------- helpers ----------------
__device__ __forceinline__ unsigned f2tf(float f) {
    unsigned u;
    asm("cvt.rna.tf32.f32 %0, %1;" : "=r"(u) : "f"(f));
    return u;
}

__device__ __forceinline__ void mma_tf32(float c[4],
                                         const unsigned a[4],
                                         const unsigned b[2]) {
    asm volatile(
        "mma.sync.aligned.m16n8k8.row.col.f32.tf32.tf32.f32 "
        "{%0,%1,%2,%3}, {%4,%5,%6,%7}, {%8,%9}, {%0,%1,%2,%3};"
        : "+f"(c[0]), "+f"(c[1]), "+f"(c[2]), "+f"(c[3])
        : "r"(a[0]), "r"(a[1]), "r"(a[2]), "r"(a[3]), "r"(b[0]), "r"(b[1]));
}

// ---------------- CSR build ----------------
__global__ void k_zero() {
    int i = blockIdx.x * blockDim.x + threadIdx.x;
    int stride = gridDim.x * blockDim.x;
    for (int j = i; j < NN; j += stride) { g_deg[j] = 0; g_cur[j] = 0; }
    if (i == 0) g_rp[NN] = EE;
}

__global__ void k_hist(const int* __restrict__ row) {
    int e = blockIdx.x * blockDim.x + threadIdx.x;
    if (e < EE) atomicAdd(&g_deg[row[e]], 1);
}

__global__ void k_scan1() {   // per-chunk sums (chunk = 1024)
    __shared__ int sred[8];
    int base = blockIdx.x * 1024;
    int local = 0;
    #pragma unroll
    for (int j = 0; j < 4; ++j) {
        int i = base + threadIdx.x + j * 256;
        if (i < NN) local += g_deg[i];
    }
    for (int off = 16; off; off >>= 1) local += __shfl_down_sync(0xffffffffu, local, off);
    if ((threadIdx.x & 31) == 0) sred[threadIdx.x >> 5] = local;
    __syncthreads();
    if (threadIdx.x == 0) {
        int s = 0;
        #pragma unroll
        for (int w = 0; w < 8; ++w) s += sred[w];
        g_part[blockIdx.x] = s;
    }
}

__global__ void k_scan2() {   // parallel exclusive scan of 49 partials
    __shared__ int s[64];
    int t = threadIdx.x;
    int v = (t < NCH) ? g_part[t] : 0;
    s[t] = v;
    __syncthreads();
    for (int off = 1; off < 64; off <<= 1) {
        int u = (t >= off) ? s[t - off] : 0;
        __syncthreads();
        s[t] += u;
        __syncthreads();
    }
    if (t < NCH) g_part[t] = s[t] - v;
}

__global__ void k_scan3() {   // per-chunk exclusive scan + offset
    __shared__ int s[1024];
    int i = blockIdx.x * 1024 + threadIdx.x;
    int v = (i < NN) ? g_deg[i] : 0;
    s[threadIdx.x] = v;
    __syncthreads();
    for (int off = 1; off < 1024; off <<= 1) {
        int t = (threadIdx.x >= (unsigned)off) ? s[threadIdx.x - off] : 0;
        __syncthreads();
        s[threadIdx.x] += t;
        __syncthreads();
    }
    if (i < NN) g_rp[i] = g_part[blockIdx.x] + s[threadIdx.x] - v;
}

__global__ void k_scatter(const int* __restrict__ row, const int* __restrict__ col,
                          const float* __restrict__ vZ, const float* __restrict__ vA) {
    int e = blockIdx.x * blockDim.x + threadIdx.x;
    if (e >= EE) return;
    int r = row[e];
    int pos = g_rp[r] + atomicAdd(&g_cur[r], 1);
    g_colP[pos] = col[e];
    g_vZ[pos]   = vZ[e];
    g_vA[pos]   = vA[e];
}

// ======== GEMM 0 (tf32 tensor core): P0 = M ⊙ (x @ W0), 50000x128x128 ========
// block tile 128x128, 256 threads (8 warps in 2(m) x 4(n)); warp tile 64x32.
__global__ void __launch_bounds__(256) k_gemm0(const float* __restrict__ x,
                                               const float* __restrict__ W0,
                                               const float* __restrict__ M) {
    __shared__ float As[128 * 32];   // [m][k^swz], swz = (m&3)<<3
    __shared__ float Bs[32 * 128];   // [k][n^swz], swz = (k&3)<<3
    int r0 = blockIdx.x * 128;
    int tid = threadIdx.x;
    int lane = tid & 31, wid = tid >> 5;
    int m0w = (wid & 1) * 64;
    int n0w = (wid >> 1) * 32;
    int g = lane >> 2, t = lane & 3;

    float acc[4][4][4];
    #pragma unroll
    for (int i = 0; i < 4; ++i)
        #pragma unroll
        for (int j = 0; j < 4; ++j)
            #pragma unroll
            for (int c = 0; c < 4; ++c) acc[i][j][c] = 0.f;

    const float4* xv = (const float4*)x;
    const float4* wv = (const float4*)W0;

    for (int kc = 0; kc < 128; kc += 32) {
        __syncthreads();
        // stage A (128 rows x 32 k), tf32-rounded, swizzled
        #pragma unroll
        for (int it = 0; it < 4; ++it) {
            int i = tid + it * 256;
            int rr = i >> 3, c4 = i & 7;
            int gr = r0 + rr;
            float4 v = (gr < NN) ? xv[gr * 32 + (kc >> 2) + c4]
                                 : make_float4(0.f, 0.f, 0.f, 0.f);
            float4 o;
            o.x = __uint_as_float(f2tf(v.x));
            o.y = __uint_as_float(f2tf(v.y));
            o.z = __uint_as_float(f2tf(v.z));
            o.w = __uint_as_float(f2tf(v.w));
            *(float4*)&As[rr * 32 + ((c4 * 4) ^ ((rr & 3) << 3))] = o;
        }
        // stage B (32 k x 128 n)
        #pragma unroll
        for (int it = 0; it < 4; ++it) {
            int i = tid + it * 256;
            int kr = i >> 5, c4 = i & 31;
            float4 v = wv[(kc + kr) * 32 + c4];
            float4 o;
            o.x = __uint_as_float(f2tf(v.x));
            o.y = __uint_as_float(f2tf(v.y));
            o.z = __uint_as_float(f2tf(v.z));
            o.w = __uint_as_float(f2tf(v.w));
            *(float4*)&Bs[kr * 128 + ((c4 * 4) ^ ((kr & 3) << 3))] = o;
        }
        __syncthreads();

        #pragma unroll
        for (int k8 = 0; k8 < 32; k8 += 8) {
            unsigned af[4][4], bf[4][2];
            #pragma unroll
            for (int mt = 0; mt < 4; ++mt) {
                int m = m0w + mt * 16 + g;
                int sw = (m & 3) << 3;
                af[mt][0] = __float_as_uint(As[m * 32 + ((k8 + t) ^ sw)]);
                af[mt][1] = __float_as_uint(As[(m + 8) * 32 + ((k8 + t) ^ sw)]);
                af[mt][2] = __float_as_uint(As[m * 32 + ((k8 + t + 4) ^ sw)]);
                af[mt][3] = __float_as_uint(As[(m + 8) * 32 + ((k8 + t + 4) ^ sw)]);
            }
            #pragma unroll
            for (int nt = 0; nt < 4; ++nt) {
                int n = n0w + nt * 8 + g;
                bf[nt][0] = __float_as_uint(Bs[(k8 + t) * 128 + (n ^ (t << 3))]);
                bf[nt][1] = __float_as_uint(Bs[(k8 + t + 4) * 128 + (n ^ (t << 3))]);
            }
            #pragma unroll
            for (int mt = 0; mt < 4; ++mt)
                #pragma unroll
                for (int nt = 0; nt < 4; ++nt)
                    mma_tf32(acc[mt][nt], af[mt], bf[nt]);
        }
    }

    // epilogue: scale by M[row], store fp32
    #pragma unroll
    for (int mt = 0; mt < 4; ++mt) {
        int rlo = r0 + m0w + mt * 16 + g;
        int rhi = rlo + 8;
        float mlo = (rlo < NN) ? M[rlo] : 0.f;
        float mhi = (rhi < NN) ? M[rhi] : 0.f;
        #pragma unroll
        for (int nt = 0; nt < 4; ++nt) {
            int cc = n0w + nt * 8 + 2 * t;
            if (rlo < NN) {
                float2 o; o.x = mlo * acc[mt][nt][0]; o.y = mlo * acc[mt][nt][1];
                *(float2*)&g_P0[rlo * 128 + cc] = o;
            }
            if (rhi < NN) {
                float2 o; o.x = mhi * acc[mt][nt][2]; o.y = mhi * acc[mt][nt][3];
                *(float2*)&g_P0[rhi * 128 + cc] = o;
            }
        }
    }
}

// -------- spmm width 128: S0[r] = sum vZ * P0[col], 4-edge unroll --------
__global__ void __launch_bounds__(256) k_spmm128() {
    int w = (blockIdx.x * 256 + threadIdx.x) >> 5;
    int lane = threadIdx.x & 31;
    if (w >= NN) return;
    int s = g_rp[w], e = g_rp[w + 1];
    float4 acc = make_float4(0.f, 0.f, 0.f, 0.f);
    const float4* Xv = (const float4*)g_P0;
    int j = s;
    for (; j + 3 < e; j += 4) {
        int c0 = g_colP[j],     c1 = g_colP[j + 1];
        int c2 = g_colP[j + 2], c3 = g_colP[j + 3];
        float v0 = g_vZ[j],     v1 = g_vZ[j + 1];
        float v2 = g_vZ[j + 2], v3 = g_vZ[j + 3];
        float4 a = Xv[c0 * 32 + lane];
        float4 b = Xv[c1 * 32 + lane];
        float4 c = Xv[c2 * 32 + lane];
        float4 d = Xv[c3 * 32 + lane];
        acc.x += v0 * a.x + v1 * b.x + v2 * c.x + v3 * d.x;
        acc.y += v0 * a.y + v1 * b.y + v2 * c.y + v3 * d.y;
        acc.z += v0 * a.z + v1 * b.z + v2 * c.z + v3 * d.z;
        acc.w += v0 * a.w + v1 * b.w + v2 * c.w + v3 * d.w;
    }
    for (; j < e; ++j) {
        int c = g_colP[j]; float v = g_vZ[j];
        float4 a = Xv[c * 32 + lane];
        acc.x += v * a.x; acc.y += v * a.y; acc.z += v * a.z; acc.w += v * a.w;
    }
    ((float4*)g_S0)[w * 32 + lane] = acc;
}

// == GEMM 1 (tf32): P1 = M ⊙ (relu(AM⊙S0 + b0) @ W1), 50000x64x128 ==
// block tile 128x64, 256 threads (8 warps in 4(m) x 2(n)); warp tile 32x32.
__global__ void __launch_bounds__(256) k_gemm1(const float* __restrict__ AM,
                                               const float* __restrict__ b0,
                                               const float* __restrict__ W1,
                                               const float* __restrict__ M) {
    __shared__ float As[128 * 32];   // relu(AM*S0+b0), tf32 bits
    __shared__ float Bs[32 * 64];
    int r0 = blockIdx.x * 128;
    int tid = threadIdx.x;
    int lane = tid & 31, wid = tid >> 5;
    int m0w = (wid & 3) * 32;
    int n0w = (wid >> 2) * 32;
    int g = lane >> 2, t = lane & 3;

    float acc[2][4][4];
    #pragma unroll
    for (int i = 0; i < 2; ++i)
        #pragma unroll
        for (int j = 0; j < 4; ++j)
            #pragma unroll
            for (int c = 0; c < 4; ++c) acc[i][j][c] = 0.f;

    const float4* sv = (const float4*)g_S0;
    const float4* bv = (const float4*)b0;
    const float4* wv = (const float4*)W1;

    for (int kc = 0; kc < 128; kc += 32) {
        __syncthreads();
        // stage A with fused relu(AM*s + b0)
        #pragma unroll
        for (int it = 0; it < 4; ++it) {
            int i = tid + it * 256;
            int rr = i >> 3, c4 = i & 7;
            int gr = r0 + rr;
            float4 o = make_float4(0.f, 0.f, 0.f, 0.f);
            if (gr < NN) {
                float4 s4 = sv[gr * 32 + (kc >> 2) + c4];
                float4 bb = bv[(kc >> 2) + c4];
                float am = AM[gr];
                o.x = fmaxf(fmaf(am, s4.x, bb.x), 0.f);
                o.y = fmaxf(fmaf(am, s4.y, bb.y), 0.f);
                o.z = fmaxf(fmaf(am, s4.z, bb.z), 0.f);
                o.w = fmaxf(fmaf(am, s4.w, bb.w), 0.f);
            }
            o.x = __uint_as_float(f2tf(o.x));
            o.y = __uint_as_float(f2tf(o.y));
            o.z = __uint_as_float(f2tf(o.z));
            o.w = __uint_as_float(f2tf(o.w));
            *(float4*)&As[rr * 32 + ((c4 * 4) ^ ((rr & 3) << 3))] = o;
        }
        // stage B (32 k x 64 n)
        #pragma unroll
        for (int it = 0; it < 2; ++it) {
            int i = tid + it * 256;
            int kr = i >> 4, c4 = i & 15;
            float4 v = wv[(kc + kr) * 16 + c4];
            float4 o;
            o.x = __uint_as_float(f2tf(v.x));
            o.y = __uint_as_float(f2tf(v.y));
            o.z = __uint_as_float(f2tf(v.z));
            o.w = __uint_as_float(f2tf(v.w));
            *(float4*)&Bs[kr * 64 + ((c4 * 4) ^ ((kr & 3) << 3))] = o;
        }
        __syncthreads();

        #pragma unroll
        for (int k8 = 0; k8 < 32; k8 += 8) {
            unsigned af[2][4], bf[4][2];
            #pragma unroll
            for (int mt = 0; mt < 2; ++mt) {
                int m = m0w + mt * 16 + g;
                int sw = (m & 3) << 3;
                af[mt][0] = __float_as_uint(As[m * 32 + ((k8 + t) ^ sw)]);
                af[mt][1] = __float_as_uint(As[(m + 8) * 32 + ((k8 + t) ^ sw)]);
                af[mt][2] = __float_as_uint(As[m * 32 + ((k8 + t + 4) ^ sw)]);
                af[mt][3] = __float_as_uint(As[(m + 8) * 32 + ((k8 + t + 4) ^ sw)]);
            }
            #pragma unroll
            for (int nt = 0; nt < 4; ++nt) {
                int n = n0w + nt * 8 + g;
                bf[nt][0] = __float_as_uint(Bs[(k8 + t) * 64 + (n ^ (t << 3))]);
                bf[nt][1] = __float_as_uint(Bs[(k8 + t + 4) * 64 + (n ^ (t << 3))]);
            }
            #pragma unroll
            for (int mt = 0; mt < 2; ++mt)
                #pragma unroll
                for (int nt = 0; nt < 4; ++nt)
                    mma_tf32(acc[mt][nt], af[mt], bf[nt]);
        }
    }

    #pragma unroll
    for (int mt = 0; mt < 2; ++mt) {
        int rlo = r0 + m0w + mt * 16 + g;
        int rhi = rlo + 8;
        float mlo = (rlo < NN) ? M[rlo] : 0.f;
        float mhi = (rhi < NN) ? M[rhi] : 0.f;
        #pragma unroll
        for (int nt = 0; nt < 4; ++nt) {
            int cc = n0w + nt * 8 + 2 * t;
            if (rlo < NN) {
                float2 o; o.x = mlo * acc[mt][nt][0]; o.y = mlo * acc[mt][nt][1];
                *(float2*)&g_P1[rlo * 64 + cc] = o;
            }
            if (rhi < NN) {
                float2 o; o.x = mhi * acc[mt][nt][2]; o.y = mhi * acc[mt][nt][3];
                *(float2*)&g_P1[rhi * 64 + cc] = o;
            }
        }
    }
}

// ------- spmm width 64: 16 lanes per row gather (float4/lane), 2 edges/step,
//         x2 unrolled; final shfl(16) combine -------
__global__ void __launch_bounds__(256) k_spmm64() {
    int w = (blockIdx.x * 256 + threadIdx.x) >> 5;
    int lane = threadIdx.x & 31;
    if (w >= NN) return;
    int half = lane >> 4;         // 0 or 1: which edge of the pair
    int sub  = lane & 15;         // float4 index within the 64-wide row
    int s = g_rp[w], e = g_rp[w + 1];
    float4 acc = make_float4(0.f, 0.f, 0.f, 0.f);
    const float4* Xv = (const float4*)g_P1;
    int j = s;
    for (; j + 3 < e; j += 4) {
        int jj0 = j + half, jj1 = j + 2 + half;
        int c0 = g_colP[jj0], c1 = g_colP[jj1];
        float v0 = g_vZ[jj0], v1 = g_vZ[jj1];
        float4 a = Xv[c0 * 16 + sub];
        float4 b = Xv[c1 * 16 + sub];
        acc.x += v0 * a.x + v1 * b.x;
        acc.y += v0 * a.y + v1 * b.y;
        acc.z += v0 * a.z + v1 * b.z;
        acc.w += v0 * a.w + v1 * b.w;
    }
    for (; j < e; j += 2) {
        int jj = j + half;
        if (jj < e) {
            int c = g_colP[jj]; float v = g_vZ[jj];
            float4 a = Xv[c * 16 + sub];
            acc.x += v * a.x; acc.y += v * a.y; acc.z += v * a.z; acc.w += v * a.w;
        }
    }
    // combine halves: lane i (<16) += lane i+16
    acc.x += __shfl_down_sync(0xffffffffu, acc.x, 16);
    acc.y += __shfl_down_sync(0xffffffffu, acc.y, 16);
    acc.z += __shfl_down_sync(0xffffffffu, acc.z, 16);
    acc.w += __shfl_down_sync(0xffffffffu, acc.w, 16);
    if (half == 0)
        ((float4*)g_S1)[w * 16 + sub] = acc;
}

// ------- GEMM 2: P2 = relu(AM⊙S1 + b1) @ W2, K=64, NO=40 (scalar) -------
__global__ void __launch_bounds__(256) k_gemm2(const float* __restrict__ AM,
                                               const float* __restrict__ b1,
                                               const float* __restrict__ W2) {
    __shared__ float Xs[32][68];
    __shared__ float Ws[64 * 40];
    int r0 = blockIdx.x * 32;
    int tid = threadIdx.x;
    const float4* sv4 = (const float4*)g_S1;
    const float4* bv4 = (const float4*)b1;
    for (int i = tid; i < 512; i += 256) {
        int rr = i >> 4, c4 = i & 15;
        int gr = r0 + rr;
        float4 v = make_float4(0.f, 0.f, 0.f, 0.f);
        if (gr < NN) {
            float4 sIn = sv4[gr * 16 + c4];
            float4 bb  = bv4[c4];
            float  am  = AM[gr];
            v.x = fmaxf(fmaf(am, sIn.x, bb.x), 0.f);
            v.y = fmaxf(fmaf(am, sIn.y, bb.y), 0.f);
            v.z = fmaxf(fmaf(am, sIn.z, bb.z), 0.f);
            v.w = fmaxf(fmaf(am, sIn.w, bb.w), 0.f);
        }
        Xs[rr][c4 * 4 + 0] = v.x;
        Xs[rr][c4 * 4 + 1] = v.y;
        Xs[rr][c4 * 4 + 2] = v.z;
        Xs[rr][c4 * 4 + 3] = v.w;
    }
    for (int i = tid; i < 64 * 40; i += 256) Ws[i] = W2[i];
    __syncthreads();
    int row = tid >> 3, cg = tid & 7;
    float acc[5] = {0.f, 0.f, 0.f, 0.f, 0.f};
    #pragma unroll 4
    for (int k = 0; k < 64; ++k) {
        float xv = Xs[row][k];
        #pragma unroll
        for (int j = 0; j < 5; ++j) acc[j] += xv * Ws[k * 40 + cg * 5 + j];
    }
    int gr = r0 + row;
    if (gr < NN) {
        #pragma unroll
        for (int j = 0; j < 5; ++j) g_P2[gr * 40 + cg * 5 + j] = acc[j];
    }
}

// ------- spmm width 40 on adj + b2 + fused log_softmax -> out -------
__global__ void __launch_bounds__(256) k_spmm40_lsm(const float* __restrict__ b2,
                                                    float* __restrict__ out) {
    int w = (blockIdx.x * 256 + threadIdx.x) >> 5;
    int lane = threadIdx.x & 31;
    if (w >= NN) return;
    int s = g_rp[w], e = g_rp[w + 1];
    bool act = lane < 20;
    float ax = 0.f, ay = 0.f;
    int j = s;
    for (; j + 1 < e; j += 2) {
        int c0 = g_colP[j], c1 = g_colP[j + 1];
        float v0 = g_vA[j], v1 = g_vA[j + 1];
        if (act) {
            float2 a = *(const float2*)&g_P2[c0 * 40 + 2 * lane];
            float2 b = *(const float2*)&g_P2[c1 * 40 + 2 * lane];
            ax += v0 * a.x + v1 * b.x;
            ay += v0 * a.y + v1 * b.y;
        }
    }
    if (j < e) {
        int c = g_colP[j];
        float v = g_vA[j];
        if (act) {
            float2 a = *(const float2*)&g_P2[c * 40 + 2 * lane];
            ax += v * a.x;
            ay += v * a.y;
        }
    }
    if (act) {
        ax += b2[2 * lane];
        ay += b2[2 * lane + 1];
    }
    float m = act ? fmaxf(ax, ay) : -INFINITY;
    for (int off = 16; off; off >>= 1) m = fmaxf(m, __shfl_xor_sync(0xffffffffu, m, off));
    float sum = act ? (expf(ax - m) + expf(ay - m)) : 0.f;
    for (int off = 16; off; off >>= 1) sum += __shfl_xor_sync(0xffffffffu, sum, off);
    float lse = m + logf(sum);
    if (act) {
        float2 o;
        o.x = ax - lse;
        o.y = ay - lse;
        *(float2*)&out[w * 40 + 2 * lane] = o;
    }
}

// ---------------- launch ----------------
extern "C" void kernel_launch(void* const* d_in, const int* in_sizes, int n_in,
                              void* d_out, int out_size) {
    const float* x    = (const float*)d_in[0];
    const float* M    = (const float*)d_in[1];
    const float* AM   = (const float*)d_in[2];
    const float* adjv = (const float*)d_in[3];
    const float* adjZ = (const float*)d_in[4];
    const float* W0   = (const float*)d_in[5];
    const float* b0   = (const float*)d_in[6];
    const float* W1   = (const float*)d_in[7];
    const float* b1   = (const float*)d_in[8];
    const float* W2   = (const float*)d_in[9];
    const float* b2   = (const float*)d_in[10];
    const int*   row  = (const int*)d_in[11];
    const int*   col  = (const int*)d_in[12];
    float* out = (float*)d_out;

    (void)in_sizes; (void)n_in; (void)out_size;

    // CSR build — gemm0 moved to 4th launch slot so the ncu fixed capture
    // window (-s 5 -c 1, which has been landing on the 4th kernel) profiles
    // a kernel that matters. gemm0 has no dependency on the CSR arrays.
    k_zero<<<98, 512>>>();
    k_hist<<<(EE + 255) / 256, 256>>>(row);
    k_scan1<<<NCH, 256>>>();
    k_gemm0<<<(NN + 127) / 128, 256>>>(x, W0, M);        // 4th launch
    k_scan2<<<1, 64>>>();
    k_scan3<<<NCH, 1024>>>();
    k_scatter<<<(EE + 255) / 256, 256>>>(row, col, adjZ, adjv);

    // layer 0 aggregation
    k_spmm128<<<(NN + 7) / 8, 256>>>();
    // layer 1
    k_gemm1<<<(NN + 127) / 128, 256>>>(AM, b0, W1, M);
    k_spmm64<<<(NN + 7) / 8, 256>>>();
    // layer 2
    k_gemm2<<<(NN + 31) / 32, 256>>>(AM, b1, W2);
    k_spmm40_lsm<<<(NN + 7) / 8, 256>>>(b2, out);
}

// round 8
// speedup vs baseline: 1.3455x; 1.0315x over previous
#include <cuda_runtime.h>
#include <math.h>

#define NN 50000
#define EE 800000
#define NF0 128
#define NF1 64
#define NF2 40
#define NCH 49   /* ceil(NN/1024) */

// ---------------- scratch (__device__ globals; allocation-free) ----------------
__device__ __align__(256) float g_P0[NN * NF0];   // M ⊙ (x @ W0)
__device__ __align__(256) float g_S0[NN * NF0];   // spmm(adjZ, P0)
__device__ __align__(256) float g_P1[NN * NF1];   // M ⊙ (h0 @ W1)
__device__ __align__(256) float g_S1[NN * NF1];   // spmm(adjZ, P1)
__device__ __align__(256) float g_P2[NN * NF2];   // h1 @ W2
__device__ __align__(256) int   g_rp[NN + 1];
__device__ __align__(256) int   g_deg[NN];
__device__ __align__(256) int   g_cur[NN];
__device__ __align__(256) int   g_colP[EE];
__device__ __align__(256) float g_vZ[EE];
__device__ __align__(256) float g_vA[EE];
__device__ __align__(256) int   g_part[NCH];

// ---------------- helpers ----------------
__device__ __forceinline__ unsigned f2tf(float f) {
    unsigned u;
    asm("cvt.rna.tf32.f32 %0, %1;" : "=r"(u) : "f"(f));
    return u;
}

__device__ __forceinline__ void mma_tf32(float c[4],
                                         const unsigned a[4],
                                         const unsigned b[2]) {
    asm volatile(
        "mma.sync.aligned.m16n8k8.row.col.f32.tf32.tf32.f32 "
        "{%0,%1,%2,%3}, {%4,%5,%6,%7}, {%8,%9}, {%0,%1,%2,%3};"
        : "+f"(c[0]), "+f"(c[1]), "+f"(c[2]), "+f"(c[3])
        : "r"(a[0]), "r"(a[1]), "r"(a[2]), "r"(a[3]), "r"(b[0]), "r"(b[1]));
}

__device__ __forceinline__ void cp_async16(void* smem_dst, const void* gsrc, int src_bytes) {
    unsigned d = (unsigned)__cvta_generic_to_shared(smem_dst);
    asm volatile("cp.async.cg.shared.global [%0], [%1], 16, %2;"
                 :: "r"(d), "l"(gsrc), "r"(src_bytes));
}
__device__ __forceinline__ void cp_commit() { asm volatile("cp.async.commit_group;"); }
__device__ __forceinline__ void cp_wait0()  { asm volatile("cp.async.wait_group 0;"); }

// ---------------- CSR build ----------------
__global__ void k_zero() {
    int i = blockIdx.x * blockDim.x + threadIdx.x;
    int stride = gridDim.x * blockDim.x;
    for (int j = i; j < NN; j += stride) { g_deg[j] = 0; g_cur[j] = 0; }
    if (i == 0) g_rp[NN] = EE;
}

__global__ void k_hist(const int* __restrict__ row) {
    int e = blockIdx.x * blockDim.x + threadIdx.x;
    if (e < EE) atomicAdd(&g_deg[row[e]], 1);
}

__global__ void k_scan1() {   // per-chunk sums (chunk = 1024)
    __shared__ int sred[8];
    int base = blockIdx.x * 1024;
    int local = 0;
    #pragma unroll
    for (int j = 0; j < 4; ++j) {
        int i = base + threadIdx.x + j * 256;
        if (i < NN) local += g_deg[i];
    }
    for (int off = 16; off; off >>= 1) local += __shfl_down_sync(0xffffffffu, local, off);
    if ((threadIdx.x & 31) == 0) sred[threadIdx.x >> 5] = local;
    __syncthreads();
    if (threadIdx.x == 0) {
        int s = 0;
        #pragma unroll
        for (int w = 0; w < 8; ++w) s += sred[w];
        g_part[blockIdx.x] = s;
    }
}

__global__ void k_scan2() {   // parallel exclusive scan of 49 partials
    __shared__ int s[64];
    int t = threadIdx.x;
    int v = (t < NCH) ? g_part[t] : 0;
    s[t] = v;
    __syncthreads();
    for (int off = 1; off < 64; off <<= 1) {
        int u = (t >= off) ? s[t - off] : 0;
        __syncthreads();
        s[t] += u;
        __syncthreads();
    }
    if (t < NCH) g_part[t] = s[t] - v;
}

__global__ void k_scan3() {   // per-chunk exclusive scan + offset
    __shared__ int s[1024];
    int i = blockIdx.x * 1024 + threadIdx.x;
    int v = (i < NN) ? g_deg[i] : 0;
    s[threadIdx.x] = v;
    __syncthreads();
    for (int off = 1; off < 1024; off <<= 1) {
        int t = (threadIdx.x >= (unsigned)off) ? s[threadIdx.x - off] : 0;
        __syncthreads();
        s[threadIdx.x] += t;
        __syncthreads();
    }
    if (i < NN) g_rp[i] = g_part[blockIdx.x] + s[threadIdx.x] - v;
}

__global__ void k_scatter(const int* __restrict__ row, const int* __restrict__ col,
                          const float* __restrict__ vZ, const float* __restrict__ vA) {
    int e = blockIdx.x * blockDim.x + threadIdx.x;
    if (e >= EE) return;
    int r = row[e];
    int pos = g_rp[r] + atomicAdd(&g_cur[r], 1);
    g_colP[pos] = col[e];
    g_vZ[pos]   = vZ[e];
    g_vA[pos]   = vA[e];
}

// ======== GEMM 0 (tf32, cp.async double-buffered): P0 = M ⊙ (x @ W0) ========
// 50000x128x128. Block tile 128x128, 256 threads (8 warps 2m x 4n), warp 64x32.
// K-chunk 16, two smem buffers, one sync per chunk. No cvt: tf32 MMA uses the
// top 19 bits of raw fp32 operands (truncation rounding).
#define KCH 16
__global__ void __launch_bounds__(256, 2) k_gemm0(const float* __restrict__ x,
                                                  const float* __restrict__ W0,
                                                  const float* __restrict__ M) {
    __shared__ float As[2][128 * 20];   // [m][k], pad-20 rows (conflict-free)
    __shared__ float Bs[2][KCH * 128];  // [k][n ^ ((k&3)<<3)]
    int r0 = blockIdx.x * 128;
    int tid = threadIdx.x;
    int lane = tid & 31, wid = tid >> 5;
    int m0w = (wid & 1) * 64;
    int n0w = (wid >> 1) * 32;
    int g = lane >> 2, t = lane & 3;

    float acc[4][4][4];
    #pragma unroll
    for (int i = 0; i < 4; ++i)
        #pragma unroll
        for (int j = 0; j < 4; ++j)
            #pragma unroll
            for (int c = 0; c < 4; ++c) acc[i][j][c] = 0.f;

    const float4* xv = (const float4*)x;
    const float4* wv = (const float4*)W0;

    // staging: A = 128 rows x 16 k = 512 float4 (2/thread); B = 16 x 128 = 512 float4.
    int a_rr = tid >> 2, a_c4 = tid & 3;          // +64 rows for second
    int b_kr = tid >> 5, b_c4 = tid & 31;         // +8 rows for second

#define STAGE(kc, buf)                                                          \
    {                                                                           \
        int _gr0 = r0 + a_rr;                                                   \
        int _gr1 = _gr0 + 64;                                                   \
        cp_async16(&As[buf][a_rr * 20 + a_c4 * 4],                              \
                   xv + (long)_gr0 * 32 + ((kc) >> 2) + a_c4,                   \
                   _gr0 < NN ? 16 : 0);                                         \
        cp_async16(&As[buf][(a_rr + 64) * 20 + a_c4 * 4],                       \
                   xv + (long)_gr1 * 32 + ((kc) >> 2) + a_c4,                   \
                   _gr1 < NN ? 16 : 0);                                         \
        cp_async16(&Bs[buf][b_kr * 128 + ((b_c4 * 4) ^ ((b_kr & 3) << 3))],     \
                   wv + ((kc) + b_kr) * 32 + b_c4, 16);                         \
        cp_async16(&Bs[buf][(b_kr + 8) * 128 + ((b_c4 * 4) ^ ((b_kr & 3) << 3))],\
                   wv + ((kc) + b_kr + 8) * 32 + b_c4, 16);                     \
        cp_commit();                                                            \
    }

    STAGE(0, 0);
    cp_wait0();
    __syncthreads();

    int buf = 0;
    for (int kc = 0; kc < 128; kc += KCH, buf ^= 1) {
        if (kc + KCH < 128) STAGE(kc + KCH, buf ^ 1);
        #pragma unroll
        for (int k8 = 0; k8 < KCH; k8 += 8) {
            unsigned af[4][4], bf[4][2];
            #pragma unroll
            for (int mt = 0; mt < 4; ++mt) {
                int m = m0w + mt * 16 + g;
                af[mt][0] = __float_as_uint(As[buf][m * 20 + k8 + t]);
                af[mt][1] = __float_as_uint(As[buf][(m + 8) * 20 + k8 + t]);
                af[mt][2] = __float_as_uint(As[buf][m * 20 + k8 + t + 4]);
                af[mt][3] = __float_as_uint(As[buf][(m + 8) * 20 + k8 + t + 4]);
            }
            #pragma unroll
            for (int nt = 0; nt < 4; ++nt) {
                int n = n0w + nt * 8 + g;
                bf[nt][0] = __float_as_uint(Bs[buf][(k8 + t) * 128 + (n ^ (t << 3))]);
                bf[nt][1] = __float_as_uint(Bs[buf][(k8 + t + 4) * 128 + (n ^ (t << 3))]);
            }
            #pragma unroll
            for (int mt = 0; mt < 4; ++mt)
                #pragma unroll
                for (int nt = 0; nt < 4; ++nt)
                    mma_tf32(acc[mt][nt], af[mt], bf[nt]);
        }
        if (kc + KCH < 128) cp_wait0();
        __syncthreads();
    }

    // epilogue: scale by M[row], store fp32
    #pragma unroll
    for (int mt = 0; mt < 4; ++mt) {
        int rlo = r0 + m0w + mt * 16 + g;
        int rhi = rlo + 8;
        float mlo = (rlo < NN) ? M[rlo] : 0.f;
        float mhi = (rhi < NN) ? M[rhi] : 0.f;
        #pragma unroll
        for (int nt = 0; nt < 4; ++nt) {
            int cc = n0w + nt * 8 + 2 * t;
            if (rlo < NN) {
                float2 o; o.x = mlo * acc[mt][nt][0]; o.y = mlo * acc[mt][nt][1];
                *(float2*)&g_P0[rlo * 128 + cc] = o;
            }
            if (rhi < NN) {
                float2 o; o.x = mhi * acc[mt][nt][2]; o.y = mhi * acc[mt][nt][3];
                *(float2*)&g_P0[rhi * 128 + cc] = o;
            }
        }
    }
}
#undef STAGE
#undef KCH

// ---------------- spmm width 128: S0[r] = sum vZ * P0[col] (R4 form) --------
__global__ void __launch_bounds__(256) k_spmm128() {
    int w = (blockIdx.x * 256 + threadIdx.x) >> 5;
    int lane = threadIdx.x & 31;
    if (w >= NN) return;
    int s = g_rp[w], e = g_rp[w + 1];
    float4 acc = make_float4(0.f, 0.f, 0.f, 0.f);
    const float4* Xv = (const float4*)g_P0;
    int j = s;
    for (; j + 1 < e; j += 2) {
        int c0 = g_colP[j], c1 = g_colP[j + 1];
        float v0 = g_vZ[j], v1 = g_vZ[j + 1];
        float4 a = Xv[c0 * 32 + lane];
        float4 b = Xv[c1 * 32 + lane];
        acc.x += v0 * a.x + v1 * b.x;
        acc.y += v0 * a.y + v1 * b.y;
        acc.z += v0 * a.z + v1 * b.z;
        acc.w += v0 * a.w + v1 * b.w;
    }
    if (j < e) {
        int c = g_colP[j]; float v = g_vZ[j];
        float4 a = Xv[c * 32 + lane];
        acc.x += v * a.x; acc.y += v * a.y; acc.z += v * a.z; acc.w += v * a.w;
    }
    ((float4*)g_S0)[w * 32 + lane] = acc;
}

// == GEMM 1 (tf32): P1 = M ⊙ (relu(AM⊙S0 + b0) @ W1), 50000x64x128 ==
// block tile 128x64, 256 threads (8 warps in 4(m) x 2(n)); warp tile 32x32.
__global__ void __launch_bounds__(256) k_gemm1(const float* __restrict__ AM,
                                               const float* __restrict__ b0,
                                               const float* __restrict__ W1,
                                               const float* __restrict__ M) {
    __shared__ float As[128 * 32];   // relu(AM*S0+b0), tf32 bits
    __shared__ float Bs[32 * 64];
    int r0 = blockIdx.x * 128;
    int tid = threadIdx.x;
    int lane = tid & 31, wid = tid >> 5;
    int m0w = (wid & 3) * 32;
    int n0w = (wid >> 2) * 32;
    int g = lane >> 2, t = lane & 3;

    float acc[2][4][4];
    #pragma unroll
    for (int i = 0; i < 2; ++i)
        #pragma unroll
        for (int j = 0; j < 4; ++j)
            #pragma unroll
            for (int c = 0; c < 4; ++c) acc[i][j][c] = 0.f;

    const float4* sv = (const float4*)g_S0;
    const float4* bv = (const float4*)b0;
    const float4* wv = (const float4*)W1;

    for (int kc = 0; kc < 128; kc += 32) {
        __syncthreads();
        // stage A with fused relu(AM*s + b0)
        #pragma unroll
        for (int it = 0; it < 4; ++it) {
            int i = tid + it * 256;
            int rr = i >> 3, c4 = i & 7;
            int gr = r0 + rr;
            float4 o = make_float4(0.f, 0.f, 0.f, 0.f);
            if (gr < NN) {
                float4 s4 = sv[gr * 32 + (kc >> 2) + c4];
                float4 bb = bv[(kc >> 2) + c4];
                float am = AM[gr];
                o.x = fmaxf(fmaf(am, s4.x, bb.x), 0.f);
                o.y = fmaxf(fmaf(am, s4.y, bb.y), 0.f);
                o.z = fmaxf(fmaf(am, s4.z, bb.z), 0.f);
                o.w = fmaxf(fmaf(am, s4.w, bb.w), 0.f);
            }
            o.x = __uint_as_float(f2tf(o.x));
            o.y = __uint_as_float(f2tf(o.y));
            o.z = __uint_as_float(f2tf(o.z));
            o.w = __uint_as_float(f2tf(o.w));
            *(float4*)&As[rr * 32 + ((c4 * 4) ^ ((rr & 3) << 3))] = o;
        }
        // stage B (32 k x 64 n)
        #pragma unroll
        for (int it = 0; it < 2; ++it) {
            int i = tid + it * 256;
            int kr = i >> 4, c4 = i & 15;
            float4 v = wv[(kc + kr) * 16 + c4];
            float4 o;
            o.x = __uint_as_float(f2tf(v.x));
            o.y = __uint_as_float(f2tf(v.y));
            o.z = __uint_as_float(f2tf(v.z));
            o.w = __uint_as_float(f2tf(v.w));
            *(float4*)&Bs[kr * 64 + ((c4 * 4) ^ ((kr & 3) << 3))] = o;
        }
        __syncthreads();

        #pragma unroll
        for (int k8 = 0; k8 < 32; k8 += 8) {
            unsigned af[2][4], bf[4][2];
            #pragma unroll
            for (int mt = 0; mt < 2; ++mt) {
                int m = m0w + mt * 16 + g;
                int sw = (m & 3) << 3;
                af[mt][0] = __float_as_uint(As[m * 32 + ((k8 + t) ^ sw)]);
                af[mt][1] = __float_as_uint(As[(m + 8) * 32 + ((k8 + t) ^ sw)]);
                af[mt][2] = __float_as_uint(As[m * 32 + ((k8 + t + 4) ^ sw)]);
                af[mt][3] = __float_as_uint(As[(m + 8) * 32 + ((k8 + t + 4) ^ sw)]);
            }
            #pragma unroll
            for (int nt = 0; nt < 4; ++nt) {
                int n = n0w + nt * 8 + g;
                bf[nt][0] = __float_as_uint(Bs[(k8 + t) * 64 + (n ^ (t << 3))]);
                bf[nt][1] = __float_as_uint(Bs[(k8 + t + 4) * 64 + (n ^ (t << 3))]);
            }
            #pragma unroll
            for (int mt = 0; mt < 2; ++mt)
                #pragma unroll
                for (int nt = 0; nt < 4; ++nt)
                    mma_tf32(acc[mt][nt], af[mt], bf[nt]);
        }
    }

    #pragma unroll
    for (int mt = 0; mt < 2; ++mt) {
        int rlo = r0 + m0w + mt * 16 + g;
        int rhi = rlo + 8;
        float mlo = (rlo < NN) ? M[rlo] : 0.f;
        float mhi = (rhi < NN) ? M[rhi] : 0.f;
        #pragma unroll
        for (int nt = 0; nt < 4; ++nt) {
            int cc = n0w + nt * 8 + 2 * t;
            if (rlo < NN) {
                float2 o; o.x = mlo * acc[mt][nt][0]; o.y = mlo * acc[mt][nt][1];
                *(float2*)&g_P1[rlo * 64 + cc] = o;
            }
            if (rhi < NN) {
                float2 o; o.x = mhi * acc[mt][nt][2]; o.y = mhi * acc[mt][nt][3];
                *(float2*)&g_P1[rhi * 64 + cc] = o;
            }
        }
    }
}

// ---------------- spmm width 64 (R4 form) ----------------
__global__ void __launch_bounds__(256) k_spmm64() {
    int w = (blockIdx.x * 256 + threadIdx.x) >> 5;
    int lane = threadIdx.x & 31;
    if (w >= NN) return;
    int s = g_rp[w], e = g_rp[w + 1];
    float ax = 0.f, ay = 0.f;
    const float2* Xv = (const float2*)g_P1;
    int j = s;
    for (; j + 1 < e; j += 2) {
        int c0 = g_colP[j], c1 = g_colP[j + 1];
        float v0 = g_vZ[j], v1 = g_vZ[j + 1];
        float2 a = Xv[c0 * 32 + lane];
        float2 b = Xv[c1 * 32 + lane];
        ax += v0 * a.x + v1 * b.x;
        ay += v0 * a.y + v1 * b.y;
    }
    if (j < e) {
        int c = g_colP[j]; float v = g_vZ[j];
        float2 a = Xv[c * 32 + lane];
        ax += v * a.x; ay += v * a.y;
    }
    float2 o; o.x = ax; o.y = ay;
    ((float2*)g_S1)[w * 32 + lane] = o;
}

// ------- GEMM 2: P2 = relu(AM⊙S1 + b1) @ W2, K=64, NO=40 (scalar) -------
__global__ void __launch_bounds__(256) k_gemm2(const float* __restrict__ AM,
                                               const float* __restrict__ b1,
                                               const float* __restrict__ W2) {
    __shared__ float Xs[32][68];
    __shared__ float Ws[64 * 40];
    int r0 = blockIdx.x * 32;
    int tid = threadIdx.x;
    const float4* sv4 = (const float4*)g_S1;
    const float4* bv4 = (const float4*)b1;
    for (int i = tid; i < 512; i += 256) {
        int rr = i >> 4, c4 = i & 15;
        int gr = r0 + rr;
        float4 v = make_float4(0.f, 0.f, 0.f, 0.f);
        if (gr < NN) {
            float4 sIn = sv4[gr * 16 + c4];
            float4 bb  = bv4[c4];
            float  am  = AM[gr];
            v.x = fmaxf(fmaf(am, sIn.x, bb.x), 0.f);
            v.y = fmaxf(fmaf(am, sIn.y, bb.y), 0.f);
            v.z = fmaxf(fmaf(am, sIn.z, bb.z), 0.f);
            v.w = fmaxf(fmaf(am, sIn.w, bb.w), 0.f);
        }
        Xs[rr][c4 * 4 + 0] = v.x;
        Xs[rr][c4 * 4 + 1] = v.y;
        Xs[rr][c4 * 4 + 2] = v.z;
        Xs[rr][c4 * 4 + 3] = v.w;
    }
    for (int i = tid; i < 64 * 40; i += 256) Ws[i] = W2[i];
    __syncthreads();
    int row = tid >> 3, cg = tid & 7;
    float acc[5] = {0.f, 0.f, 0.f, 0.f, 0.f};
    #pragma unroll 4
    for (int k = 0; k < 64; ++k) {
        float xv = Xs[row][k];
        #pragma unroll
        for (int j = 0; j < 5; ++j) acc[j] += xv * Ws[k * 40 + cg * 5 + j];
    }
    int gr = r0 + row;
    if (gr < NN) {
        #pragma unroll
        for (int j = 0; j < 5; ++j) g_P2[gr * 40 + cg * 5 + j] = acc[j];
    }
}

// ------- spmm width 40 on adj + b2 + fused log_softmax -> out -------
__global__ void __launch_bounds__(256) k_spmm40_lsm(const float* __restrict__ b2,
                                                    float* __restrict__ out) {
    int w = (blockIdx.x * 256 + threadIdx.x) >> 5;
    int lane = threadIdx.x & 31;
    if (w >= NN) return;
    int s = g_rp[w], e = g_rp[w + 1];
    bool act = lane < 20;
    float ax = 0.f, ay = 0.f;
    int j = s;
    for (; j + 1 < e; j += 2) {
        int c0 = g_colP[j], c1 = g_colP[j + 1];
        float v0 = g_vA[j], v1 = g_vA[j + 1];
        if (act) {
            float2 a = *(const float2*)&g_P2[c0 * 40 + 2 * lane];
            float2 b = *(const float2*)&g_P2[c1 * 40 + 2 * lane];
            ax += v0 * a.x + v1 * b.x;
            ay += v0 * a.y + v1 * b.y;
        }
    }
    if (j < e) {
        int c = g_colP[j];
        float v = g_vA[j];
        if (act) {
            float2 a = *(const float2*)&g_P2[c * 40 + 2 * lane];
            ax += v * a.x;
            ay += v * a.y;
        }
    }
    if (act) {
        ax += b2[2 * lane];
        ay += b2[2 * lane + 1];
    }
    float m = act ? fmaxf(ax, ay) : -INFINITY;
    for (int off = 16; off; off >>= 1) m = fmaxf(m, __shfl_xor_sync(0xffffffffu, m, off));
    float sum = act ? (expf(ax - m) + expf(ay - m)) : 0.f;
    for (int off = 16; off; off >>= 1) sum += __shfl_xor_sync(0xffffffffu, sum, off);
    float lse = m + logf(sum);
    if (act) {
        float2 o;
        o.x = ax - lse;
        o.y = ay - lse;
        *(float2*)&out[w * 40 + 2 * lane] = o;
    }
}

// ---------------- launch ----------------
extern "C" void kernel_launch(void* const* d_in, const int* in_sizes, int n_in,
                              void* d_out, int out_size) {
    const float* x    = (const float*)d_in[0];
    const float* M    = (const float*)d_in[1];
    const float* AM   = (const float*)d_in[2];
    const float* adjv = (const float*)d_in[3];
    const float* adjZ = (const float*)d_in[4];
    const float* W0   = (const float*)d_in[5];
    const float* b0   = (const float*)d_in[6];
    const float* W1   = (const float*)d_in[7];
    const float* b1   = (const float*)d_in[8];
    const float* W2   = (const float*)d_in[9];
    const float* b2   = (const float*)d_in[10];
    const int*   row  = (const int*)d_in[11];
    const int*   col  = (const int*)d_in[12];
    float* out = (float*)d_out;

    (void)in_sizes; (void)n_in; (void)out_size;

    // CSR build — gemm0 kept in the 4th launch slot (ncu capture window).
    k_zero<<<98, 512>>>();
    k_hist<<<(EE + 255) / 256, 256>>>(row);
    k_scan1<<<NCH, 256>>>();
    k_gemm0<<<(NN + 127) / 128, 256>>>(x, W0, M);        // 4th launch
    k_scan2<<<1, 64>>>();
    k_scan3<<<NCH, 1024>>>();
    k_scatter<<<(EE + 255) / 256, 256>>>(row, col, adjZ, adjv);

    // layer 0 aggregation
    k_spmm128<<<(NN + 7) / 8, 256>>>();
    // layer 1
    k_gemm1<<<(NN + 127) / 128, 256>>>(AM, b0, W1, M);
    k_spmm64<<<(NN + 7) / 8, 256>>>();
    // layer 2
    k_gemm2<<<(NN + 31) / 32, 256>>>(AM, b1, W2);
    k_spmm40_lsm<<<(NN + 7) / 8, 256>>>(b2, out);
}

// round 10
// speedup vs baseline: 1.3997x; 1.0403x over previous
#include <cuda_runtime.h>
#include <math.h>

#define NN 50000
#define EE 800000
#define NF0 128
#define NF1 64
#define NF2 40
#define NCH 49   /* ceil(NN/1024) */

// ---------------- scratch (__device__ globals; allocation-free) ----------------
// NOTE: device globals are zero-initialized at module load. g_deg/g_cur are
// re-zeroed at the END of each kernel_launch (tail of k_spmm40_lsm), so every
// call (and every graph replay) starts with them zeroed.
__device__ __align__(256) float g_P0[NN * NF0];   // M ⊙ (x @ W0)
__device__ __align__(256) float g_S0[NN * NF0];   // H0 = relu(AM⊙spmm + b0)
__device__ __align__(256) float g_P1[NN * NF1];   // M ⊙ (H0 @ W1)
__device__ __align__(256) float g_S1[NN * NF1];   // H1 = relu(AM⊙spmm + b1)
__device__ __align__(256) float g_P2[NN * NF2];   // H1 @ W2
__device__ __align__(256) int   g_rp[NN + 1];
__device__ __align__(256) int   g_deg[NN];
__device__ __align__(256) int   g_cur[NN];
__device__ __align__(256) int   g_colP[EE];
__device__ __align__(256) float g_vZ[EE];
__device__ __align__(256) float g_vA[EE];
__device__ __align__(256) int   g_part[NCH];

// ---------------- helpers ----------------
__device__ __forceinline__ unsigned f2tf(float f) {
    unsigned u;
    asm("cvt.rna.tf32.f32 %0, %1;" : "=r"(u) : "f"(f));
    return u;
}

__device__ __forceinline__ void mma_tf32(float c[4],
                                         const unsigned a[4],
                                         const unsigned b[2]) {
    asm volatile(
        "mma.sync.aligned.m16n8k8.row.col.f32.tf32.tf32.f32 "
        "{%0,%1,%2,%3}, {%4,%5,%6,%7}, {%8,%9}, {%0,%1,%2,%3};"
        : "+f"(c[0]), "+f"(c[1]), "+f"(c[2]), "+f"(c[3])
        : "r"(a[0]), "r"(a[1]), "r"(a[2]), "r"(a[3]), "r"(b[0]), "r"(b[1]));
}

__device__ __forceinline__ void cp_async16(void* smem_dst, const void* gsrc, int src_bytes) {
    unsigned d = (unsigned)__cvta_generic_to_shared(smem_dst);
    asm volatile("cp.async.cg.shared.global [%0], [%1], 16, %2;"
                 :: "r"(d), "l"(gsrc), "r"(src_bytes));
}
__device__ __forceinline__ void cp_commit() { asm volatile("cp.async.commit_group;"); }
__device__ __forceinline__ void cp_wait0()  { asm volatile("cp.async.wait_group 0;"); }

// ---------------- CSR build ----------------
__global__ void k_hist(const int* __restrict__ row) {
    int e = blockIdx.x * blockDim.x + threadIdx.x;
    if (e < EE) atomicAdd(&g_deg[row[e]], 1);
}

__global__ void k_scan1() {   // per-chunk sums (chunk = 1024)
    __shared__ int sred[8];
    int base = blockIdx.x * 1024;
    int local = 0;
    #pragma unroll
    for (int j = 0; j < 4; ++j) {
        int i = base + threadIdx.x + j * 256;
        if (i < NN) local += g_deg[i];
    }
    for (int off = 16; off; off >>= 1) local += __shfl_down_sync(0xffffffffu, local, off);
    if ((threadIdx.x & 31) == 0) sred[threadIdx.x >> 5] = local;
    __syncthreads();
    if (threadIdx.x == 0) {
        int s = 0;
        #pragma unroll
        for (int w = 0; w < 8; ++w) s += sred[w];
        g_part[blockIdx.x] = s;
    }
}

// fused scan2+scan3: each block computes its own chunk offset (sum of earlier
// chunk partials) then the in-chunk exclusive scan.
__global__ void k_scan23() {
    __shared__ int s[1024];
    __shared__ int psum[2];
    int bid = blockIdx.x;
    int tid = threadIdx.x;
    int i = bid * 1024 + tid;
    int v = (i < NN) ? g_deg[i] : 0;
    s[tid] = v;
    if (tid < 64) {
        int p = (tid < bid) ? g_part[tid] : 0;   // bid <= 48 < 64
        for (int off = 16; off; off >>= 1) p += __shfl_down_sync(0xffffffffu, p, off);
        if ((tid & 31) == 0) psum[tid >> 5] = p;
    }
    __syncthreads();
    int off0 = psum[0] + psum[1];
    for (int off = 1; off < 1024; off <<= 1) {
        int t = (tid >= (unsigned)off) ? s[tid - off] : 0;
        __syncthreads();
        s[tid] += t;
        __syncthreads();
    }
    if (i < NN) g_rp[i] = off0 + s[tid] - v;
    if (bid == 0 && tid == 0) g_rp[NN] = EE;
}

__global__ void k_scatter(const int* __restrict__ row, const int* __restrict__ col,
                          const float* __restrict__ vZ, const float* __restrict__ vA) {
    int e = blockIdx.x * blockDim.x + threadIdx.x;
    if (e >= EE) return;
    int r = row[e];
    int pos = g_rp[r] + atomicAdd(&g_cur[r], 1);
    g_colP[pos] = col[e];
    g_vZ[pos]   = vZ[e];
    g_vA[pos]   = vA[e];
}

// ======== GEMM 0 (tf32, cp.async double-buffered): P0 = M ⊙ (x @ W0) ========
// 50000x128x128. Block tile 128x128, 256 threads (8 warps 2m x 4n), warp 64x32.
// K-chunk 16, two smem buffers. RNA tf32 rounding applied at fragment load.
#define KCH 16
__global__ void __launch_bounds__(256, 2) k_gemm0(const float* __restrict__ x,
                                                  const float* __restrict__ W0,
                                                  const float* __restrict__ M) {
    __shared__ __align__(16) float As[2][128 * 20];   // [m][k], pad-20 (conflict-free)
    __shared__ __align__(16) float Bs[2][KCH * 128];  // [k][n ^ ((k&3)<<3)]
    int r0 = blockIdx.x * 128;
    int tid = threadIdx.x;
    int lane = tid & 31, wid = tid >> 5;
    int m0w = (wid & 1) * 64;
    int n0w = (wid >> 1) * 32;
    int g = lane >> 2, t = lane & 3;

    float acc[4][4][4];
    #pragma unroll
    for (int i = 0; i < 4; ++i)
        #pragma unroll
        for (int j = 0; j < 4; ++j)
            #pragma unroll
            for (int c = 0; c < 4; ++c) acc[i][j][c] = 0.f;

    const float4* xv = (const float4*)x;
    const float4* wv = (const float4*)W0;

    int a_rr = tid >> 2, a_c4 = tid & 3;
    int b_kr = tid >> 5, b_c4 = tid & 31;

#define STAGE0(kc, buf)                                                          \
    {                                                                            \
        int _gr0 = r0 + a_rr;                                                    \
        int _gr1 = _gr0 + 64;                                                    \
        cp_async16(&As[buf][a_rr * 20 + a_c4 * 4],                               \
                   xv + (long)_gr0 * 32 + ((kc) >> 2) + a_c4,                    \
                   _gr0 < NN ? 16 : 0);                                          \
        cp_async16(&As[buf][(a_rr + 64) * 20 + a_c4 * 4],                        \
                   xv + (long)_gr1 * 32 + ((kc) >> 2) + a_c4,                    \
                   _gr1 < NN ? 16 : 0);                                          \
        cp_async16(&Bs[buf][b_kr * 128 + ((b_c4 * 4) ^ ((b_kr & 3) << 3))],      \
                   wv + ((kc) + b_kr) * 32 + b_c4, 16);                          \
        cp_async16(&Bs[buf][(b_kr + 8) * 128 + ((b_c4 * 4) ^ ((b_kr & 3) << 3))],\
                   wv + ((kc) + b_kr + 8) * 32 + b_c4, 16);                      \
        cp_commit();                                                             \
    }

    STAGE0(0, 0);
    cp_wait0();
    __syncthreads();

    int buf = 0;
    for (int kc = 0; kc < 128; kc += KCH, buf ^= 1) {
        if (kc + KCH < 128) STAGE0(kc + KCH, buf ^ 1);
        #pragma unroll
        for (int k8 = 0; k8 < KCH; k8 += 8) {
            unsigned af[4][4], bf[4][2];
            #pragma unroll
            for (int mt = 0; mt < 4; ++mt) {
                int m = m0w + mt * 16 + g;
                af[mt][0] = f2tf(As[buf][m * 20 + k8 + t]);
                af[mt][1] = f2tf(As[buf][(m + 8) * 20 + k8 + t]);
                af[mt][2] = f2tf(As[buf][m * 20 + k8 + t + 4]);
                af[mt][3] = f2tf(As[buf][(m + 8) * 20 + k8 + t + 4]);
            }
            #pragma unroll
            for (int nt = 0; nt < 4; ++nt) {
                int n = n0w + nt * 8 + g;
                bf[nt][0] = f2tf(Bs[buf][(k8 + t) * 128 + (n ^ (t << 3))]);
                bf[nt][1] = f2tf(Bs[buf][(k8 + t + 4) * 128 + (n ^ (t << 3))]);
            }
            #pragma unroll
            for (int mt = 0; mt < 4; ++mt)
                #pragma unroll
                for (int nt = 0; nt < 4; ++nt)
                    mma_tf32(acc[mt][nt], af[mt], bf[nt]);
        }
        if (kc + KCH < 128) cp_wait0();
        __syncthreads();
    }

    #pragma unroll
    for (int mt = 0; mt < 4; ++mt) {
        int rlo = r0 + m0w + mt * 16 + g;
        int rhi = rlo + 8;
        float mlo = (rlo < NN) ? M[rlo] : 0.f;
        float mhi = (rhi < NN) ? M[rhi] : 0.f;
        #pragma unroll
        for (int nt = 0; nt < 4; ++nt) {
            int cc = n0w + nt * 8 + 2 * t;
            if (rlo < NN) {
                float2 o; o.x = mlo * acc[mt][nt][0]; o.y = mlo * acc[mt][nt][1];
                *(float2*)&g_P0[rlo * 128 + cc] = o;
            }
            if (rhi < NN) {
                float2 o; o.x = mhi * acc[mt][nt][2]; o.y = mhi * acc[mt][nt][3];
                *(float2*)&g_P0[rhi * 128 + cc] = o;
            }
        }
    }
}
#undef STAGE0
#undef KCH

// -- spmm width 128 + fused relu(AM⊙s + b0): H0 -> g_S0 --
__global__ void __launch_bounds__(256) k_spmm128(const float* __restrict__ AM,
                                                 const float* __restrict__ b0) {
    int w = (blockIdx.x * 256 + threadIdx.x) >> 5;
    int lane = threadIdx.x & 31;
    if (w >= NN) return;
    int s = g_rp[w], e = g_rp[w + 1];
    float4 acc = make_float4(0.f, 0.f, 0.f, 0.f);
    const float4* Xv = (const float4*)g_P0;
    int j = s;
    for (; j + 1 < e; j += 2) {
        int c0 = g_colP[j], c1 = g_colP[j + 1];
        float v0 = g_vZ[j], v1 = g_vZ[j + 1];
        float4 a = Xv[c0 * 32 + lane];
        float4 b = Xv[c1 * 32 + lane];
        acc.x += v0 * a.x + v1 * b.x;
        acc.y += v0 * a.y + v1 * b.y;
        acc.z += v0 * a.z + v1 * b.z;
        acc.w += v0 * a.w + v1 * b.w;
    }
    if (j < e) {
        int c = g_colP[j]; float v = g_vZ[j];
        float4 a = Xv[c * 32 + lane];
        acc.x += v * a.x; acc.y += v * a.y; acc.z += v * a.z; acc.w += v * a.w;
    }
    float am = AM[w];
    float4 bb = ((const float4*)b0)[lane];
    float4 o;
    o.x = fmaxf(fmaf(am, acc.x, bb.x), 0.f);
    o.y = fmaxf(fmaf(am, acc.y, bb.y), 0.f);
    o.z = fmaxf(fmaf(am, acc.z, bb.z), 0.f);
    o.w = fmaxf(fmaf(am, acc.w, bb.w), 0.f);
    ((float4*)g_S0)[w * 32 + lane] = o;
}

// ======== GEMM 1 (tf32, cp.async double-buffered): P1 = M ⊙ (H0 @ W1) ========
// 50000x64x128. Block tile 128x64, 256 threads (8 warps 4m x 2n), warp 32x32.
#define KCH1 16
__global__ void __launch_bounds__(256, 2) k_gemm1(const float* __restrict__ W1,
                                                  const float* __restrict__ M) {
    __shared__ __align__(16) float As[2][128 * 20];   // H0 tile, pad-20
    __shared__ __align__(16) float Bs[2][KCH1 * 64];  // [k][n ^ ((k&3)<<3)]
    int r0 = blockIdx.x * 128;
    int tid = threadIdx.x;
    int lane = tid & 31, wid = tid >> 5;
    int m0w = (wid & 3) * 32;
    int n0w = (wid >> 2) * 32;
    int g = lane >> 2, t = lane & 3;

    float acc[2][4][4];
    #pragma unroll
    for (int i = 0; i < 2; ++i)
        #pragma unroll
        for (int j = 0; j < 4; ++j)
            #pragma unroll
            for (int c = 0; c < 4; ++c) acc[i][j][c] = 0.f;

    const float4* hv = (const float4*)g_S0;   // H0, 32 float4 per row
    const float4* wv = (const float4*)W1;     // 16 float4 per row

    int a_rr = tid >> 2, a_c4 = tid & 3;      // A: 2 cp.async per thread
    int b_kr = tid >> 4, b_c4 = tid & 15;     // B: 1 cp.async per thread

#define STAGE1(kc, buf)                                                          \
    {                                                                            \
        int _gr0 = r0 + a_rr;                                                    \
        int _gr1 = _gr0 + 64;                                                    \
        cp_async16(&As[buf][a_rr * 20 + a_c4 * 4],                               \
                   hv + (long)_gr0 * 32 + ((kc) >> 2) + a_c4,                    \
                   _gr0 < NN ? 16 : 0);                                          \
        cp_async16(&As[buf][(a_rr + 64) * 20 + a_c4 * 4],                        \
                   hv + (long)_gr1 * 32 + ((kc) >> 2) + a_c4,                    \
                   _gr1 < NN ? 16 : 0);                                          \
        cp_async16(&Bs[buf][b_kr * 64 + ((b_c4 * 4) ^ ((b_kr & 3) << 3))],       \
                   wv + ((kc) + b_kr) * 16 + b_c4, 16);                          \
        cp_commit();                                                             \
    }

    STAGE1(0, 0);
    cp_wait0();
    __syncthreads();

    int buf = 0;
    for (int kc = 0; kc < 128; kc += KCH1, buf ^= 1) {
        if (kc + KCH1 < 128) STAGE1(kc + KCH1, buf ^ 1);
        #pragma unroll
        for (int k8 = 0; k8 < KCH1; k8 += 8) {
            unsigned af[2][4], bf[4][2];
            #pragma unroll
            for (int mt = 0; mt < 2; ++mt) {
                int m = m0w + mt * 16 + g;
                af[mt][0] = f2tf(As[buf][m * 20 + k8 + t]);
                af[mt][1] = f2tf(As[buf][(m + 8) * 20 + k8 + t]);
                af[mt][2] = f2tf(As[buf][m * 20 + k8 + t + 4]);
                af[mt][3] = f2tf(As[buf][(m + 8) * 20 + k8 + t + 4]);
            }
            #pragma unroll
            for (int nt = 0; nt < 4; ++nt) {
                int n = n0w + nt * 8 + g;
                bf[nt][0] = f2tf(Bs[buf][(k8 + t) * 64 + (n ^ (t << 3))]);
                bf[nt][1] = f2tf(Bs[buf][(k8 + t + 4) * 64 + (n ^ (t << 3))]);
            }
            #pragma unroll
            for (int mt = 0; mt < 2; ++mt)
                #pragma unroll
                for (int nt = 0; nt < 4; ++nt)
                    mma_tf32(acc[mt][nt], af[mt], bf[nt]);
        }
        if (kc + KCH1 < 128) cp_wait0();
        __syncthreads();
    }

    #pragma unroll
    for (int mt = 0; mt < 2; ++mt) {
        int rlo = r0 + m0w + mt * 16 + g;
        int rhi = rlo + 8;
        float mlo = (rlo < NN) ? M[rlo] : 0.f;
        float mhi = (rhi < NN) ? M[rhi] : 0.f;
        #pragma unroll
        for (int nt = 0; nt < 4; ++nt) {
            int cc = n0w + nt * 8 + 2 * t;
            if (rlo < NN) {
                float2 o; o.x = mlo * acc[mt][nt][0]; o.y = mlo * acc[mt][nt][1];
                *(float2*)&g_P1[rlo * 64 + cc] = o;
            }
            if (rhi < NN) {
                float2 o; o.x = mhi * acc[mt][nt][2]; o.y = mhi * acc[mt][nt][3];
                *(float2*)&g_P1[rhi * 64 + cc] = o;
            }
        }
    }
}
#undef STAGE1
#undef KCH1

// -- spmm width 64 + fused relu(AM⊙s + b1): H1 -> g_S1 --
__global__ void __launch_bounds__(256) k_spmm64(const float* __restrict__ AM,
                                                const float* __restrict__ b1) {
    int w = (blockIdx.x * 256 + threadIdx.x) >> 5;
    int lane = threadIdx.x & 31;
    if (w >= NN) return;
    int s = g_rp[w], e = g_rp[w + 1];
    float ax = 0.f, ay = 0.f;
    const float2* Xv = (const float2*)g_P1;
    int j = s;
    for (; j + 1 < e; j += 2) {
        int c0 = g_colP[j], c1 = g_colP[j + 1];
        float v0 = g_vZ[j], v1 = g_vZ[j + 1];
        float2 a = Xv[c0 * 32 + lane];
        float2 b = Xv[c1 * 32 + lane];
        ax += v0 * a.x + v1 * b.x;
        ay += v0 * a.y + v1 * b.y;
    }
    if (j < e) {
        int c = g_colP[j]; float v = g_vZ[j];
        float2 a = Xv[c * 32 + lane];
        ax += v * a.x; ay += v * a.y;
    }
    float am = AM[w];
    float2 bb = ((const float2*)b1)[lane];
    float2 o;
    o.x = fmaxf(fmaf(am, ax, bb.x), 0.f);
    o.y = fmaxf(fmaf(am, ay, bb.y), 0.f);
    ((float2*)g_S1)[w * 32 + lane] = o;
}

// ------- GEMM 2: P2 = H1 @ W2, K=64, NO=40 (scalar; H1 pre-activated) -------
__global__ void __launch_bounds__(256) k_gemm2(const float* __restrict__ W2) {
    __shared__ float Xs[32][68];
    __shared__ float Ws[64 * 40];
    int r0 = blockIdx.x * 32;
    int tid = threadIdx.x;
    const float4* sv4 = (const float4*)g_S1;
    for (int i = tid; i < 512; i += 256) {
        int rr = i >> 4, c4 = i & 15;
        int gr = r0 + rr;
        float4 v = (gr < NN) ? sv4[gr * 16 + c4] : make_float4(0.f, 0.f, 0.f, 0.f);
        Xs[rr][c4 * 4 + 0] = v.x;
        Xs[rr][c4 * 4 + 1] = v.y;
        Xs[rr][c4 * 4 + 2] = v.z;
        Xs[rr][c4 * 4 + 3] = v.w;
    }
    for (int i = tid; i < 64 * 40; i += 256) Ws[i] = W2[i];
    __syncthreads();
    int row = tid >> 3, cg = tid & 7;
    float acc[5] = {0.f, 0.f, 0.f, 0.f, 0.f};
    #pragma unroll 4
    for (int k = 0; k < 64; ++k) {
        float xv = Xs[row][k];
        #pragma unroll
        for (int j = 0; j < 5; ++j) acc[j] += xv * Ws[k * 40 + cg * 5 + j];
    }
    int gr = r0 + row;
    if (gr < NN) {
        #pragma unroll
        for (int j = 0; j < 5; ++j) g_P2[gr * 40 + cg * 5 + j] = acc[j];
    }
}

// -- spmm width 40 on adj + b2 + fused log_softmax -> out; also re-zeros
//    g_deg/g_cur for the next call/replay --
__global__ void __launch_bounds__(256) k_spmm40_lsm(const float* __restrict__ b2,
                                                    float* __restrict__ out) {
    int gi = blockIdx.x * 256 + threadIdx.x;
    if (gi < NN) { g_deg[gi] = 0; g_cur[gi] = 0; }   // cleanup for next launch
    int w = gi >> 5;
    int lane = threadIdx.x & 31;
    if (w >= NN) return;
    int s = g_rp[w], e = g_rp[w + 1];
    bool act = lane < 20;
    float ax = 0.f, ay = 0.f;
    int j = s;
    for (; j + 1 < e; j += 2) {
        int c0 = g_colP[j], c1 = g_colP[j + 1];
        float v0 = g_vA[j], v1 = g_vA[j + 1];
        if (act) {
            float2 a = *(const float2*)&g_P2[c0 * 40 + 2 * lane];
            float2 b = *(const float2*)&g_P2[c1 * 40 + 2 * lane];
            ax += v0 * a.x + v1 * b.x;
            ay += v0 * a.y + v1 * b.y;
        }
    }
    if (j < e) {
        int c = g_colP[j];
        float v = g_vA[j];
        if (act) {
            float2 a = *(const float2*)&g_P2[c * 40 + 2 * lane];
            ax += v * a.x;
            ay += v * a.y;
        }
    }
    if (act) {
        ax += b2[2 * lane];
        ay += b2[2 * lane + 1];
    }
    float m = act ? fmaxf(ax, ay) : -INFINITY;
    for (int off = 16; off; off >>= 1) m = fmaxf(m, __shfl_xor_sync(0xffffffffu, m, off));
    float sum = act ? (expf(ax - m) + expf(ay - m)) : 0.f;
    for (int off = 16; off; off >>= 1) sum += __shfl_xor_sync(0xffffffffu, sum, off);
    float lse = m + logf(sum);
    if (act) {
        float2 o;
        o.x = ax - lse;
        o.y = ay - lse;
        *(float2*)&out[w * 40 + 2 * lane] = o;
    }
}

// ---------------- launch ----------------
extern "C" void kernel_launch(void* const* d_in, const int* in_sizes, int n_in,
                              void* d_out, int out_size) {
    const float* x    = (const float*)d_in[0];
    const float* M    = (const float*)d_in[1];
    const float* AM   = (const float*)d_in[2];
    const float* adjv = (const float*)d_in[3];
    const float* adjZ = (const float*)d_in[4];
    const float* W0   = (const float*)d_in[5];
    const float* b0   = (const float*)d_in[6];
    const float* W1   = (const float*)d_in[7];
    const float* b1   = (const float*)d_in[8];
    const float* W2   = (const float*)d_in[9];
    const float* b2   = (const float*)d_in[10];
    const int*   row  = (const int*)d_in[11];
    const int*   col  = (const int*)d_in[12];
    float* out = (float*)d_out;

    (void)in_sizes; (void)n_in; (void)out_size;

    // 10 launches. gemm0 stays in the 4th slot (ncu capture window).
    k_hist<<<(EE + 255) / 256, 256>>>(row);
    k_scan1<<<NCH, 256>>>();
    k_scan23<<<NCH, 1024>>>();
    k_gemm0<<<(NN + 127) / 128, 256>>>(x, W0, M);        // 4th launch
    k_scatter<<<(EE + 255) / 256, 256>>>(row, col, adjZ, adjv);

    k_spmm128<<<(NN + 7) / 8, 256>>>(AM, b0);
    k_gemm1<<<(NN + 127) / 128, 256>>>(W1, M);
    k_spmm64<<<(NN + 7) / 8, 256>>>(AM, b1);
    k_gemm2<<<(NN + 31) / 32, 256>>>(W2);
    k_spmm40_lsm<<<(NN + 7) / 8, 256>>>(b2, out);
}